// round 12
// baseline (speedup 1.0000x reference)
#include <cuda_runtime.h>
#include <cstdint>

// Problem constants
#define EDIM 2048
#define HNUM 16
#define NB   4
#define SLEN 2048
#define TLEN 2048
#define DHEAD 128

#define NEG_INF (__int_as_float(0xff800000))

// Scratch (allocation-free rule: __device__ globals)
__device__ float g_Q [(size_t)NB * SLEN * EDIM];            // 64 MB (tf32-rounded)
__device__ float g_K [(size_t)NB * TLEN * EDIM];            // 64 MB (tf32-rounded)
__device__ float g_V [(size_t)NB * TLEN * EDIM];            // 64 MB (tf32-rounded)
__device__ float g_AO[(size_t)NB * SLEN * EDIM];            // 64 MB (tf32-rounded)
__device__ int   g_mask_allones;

// fp32 -> tf32 round-to-nearest
__device__ __forceinline__ uint32_t f2tf(float f) {
    uint32_t u;
    asm("cvt.rna.tf32.f32 %0, %1;" : "=r"(u) : "f"(f));
    return u;
}

__device__ __forceinline__ void mma8(float& c0, float& c1, float& c2, float& c3,
                                     uint32_t a0, uint32_t a1, uint32_t a2, uint32_t a3,
                                     uint32_t b0, uint32_t b1) {
    asm volatile(
        "mma.sync.aligned.m16n8k8.row.col.f32.tf32.tf32.f32 "
        "{%0,%1,%2,%3},{%4,%5,%6,%7},{%8,%9},{%0,%1,%2,%3};"
        : "+f"(c0), "+f"(c1), "+f"(c2), "+f"(c3)
        : "r"(a0), "r"(a1), "r"(a2), "r"(a3), "r"(b0), "r"(b1));
}

__device__ __forceinline__ uint32_t smem_u32(const void* p) {
    uint32_t a;
    asm("{ .reg .u64 t; cvta.to.shared.u64 t, %1; cvt.u32.u64 %0, t; }" : "=r"(a) : "l"(p));
    return a;
}
__device__ __forceinline__ void cp16(uint32_t dst, const void* src) {
    asm volatile("cp.async.cg.shared.global [%0], [%1], 16;" :: "r"(dst), "l"(src));
}

// ---------------------------------------------------------------------------
// Tensor-core tf32 GEMM (TRANSB form): C[m][n] = sum_k A[m][k]*B[n][k]
// 128x128 CTA tile, kChunk=16, 256 threads, double-buffered SMEM.
// SMEM k-interleaved layout: within each 8-k block, word order k' = 2t + u
// (t = k&3, u = (k>>2)&1) so each MMA fragment's (k=t, k=t+4) pair is one
// LDS.64. RND: store C rounded to tf32.
// ---------------------------------------------------------------------------
#define ASTRIDE 20

template<bool HAS_BIAS, bool RND>
__global__ void __launch_bounds__(256, 2)
gemm_tc(const float* __restrict__ A, int lda,
        const float* __restrict__ B, int ldb,
        float*       __restrict__ C, int ldc,
        const float* __restrict__ bias, int K)
{
    __shared__ uint32_t As[2][128 * ASTRIDE];
    __shared__ uint32_t Bs[2][128 * ASTRIDE];

    const int tid  = threadIdx.x;
    const int lane = tid & 31;
    const int warp = tid >> 5;
    const int wm   = warp & 3;
    const int wn   = warp >> 2;
    const int m0   = blockIdx.y * 128;
    const int n0   = blockIdx.x * 128;

    const int lr = tid >> 2;           // 0..63
    const int lk = (tid & 3) << 2;     // 0,4,8,12
    const int g  = lane >> 2;
    const int t  = lane & 3;

    // writer dest base within a row: kb*8 + u
    const int wbase = ((lk >> 3) << 3) + ((lk >> 2) & 1);

    float acc[2][8][4];
#pragma unroll
    for (int i = 0; i < 2; i++)
#pragma unroll
        for (int j = 0; j < 8; j++)
#pragma unroll
            for (int q = 0; q < 4; q++) acc[i][j][q] = 0.0f;

    const int nch = K >> 4;

    // ---- initial tile load (chunk 0) ----
#pragma unroll
    for (int i = 0; i < 2; i++) {
        int r = lr + i * 64;
        float4 v = *(const float4*)(A + (size_t)(m0 + r) * lda + lk);
        uint32_t* d = &As[0][r * ASTRIDE + wbase];
        d[0] = f2tf(v.x); d[2] = f2tf(v.y); d[4] = f2tf(v.z); d[6] = f2tf(v.w);
        float4 w = *(const float4*)(B + (size_t)(n0 + r) * ldb + lk);
        uint32_t* e = &Bs[0][r * ASTRIDE + wbase];
        e[0] = f2tf(w.x); e[2] = f2tf(w.y); e[4] = f2tf(w.z); e[6] = f2tf(w.w);
    }
    __syncthreads();

    int buf = 0;
    for (int ch = 0; ch < nch; ch++) {
        const bool nxt = (ch + 1 < nch);
        const int  k1  = (ch + 1) << 4;

        float4 ra[2], rb[2];
        if (nxt) {
#pragma unroll
            for (int i = 0; i < 2; i++) {
                int r = lr + i * 64;
                ra[i] = *(const float4*)(A + (size_t)(m0 + r) * lda + k1 + lk);
                rb[i] = *(const float4*)(B + (size_t)(n0 + r) * ldb + k1 + lk);
            }
        }

        // ---- compute on current buffer ----
        const uint32_t* as = As[buf];
        const uint32_t* bs = Bs[buf];
#pragma unroll
        for (int ks = 0; ks < 16; ks += 8) {
            uint32_t af[2][4];
#pragma unroll
            for (int mi = 0; mi < 2; mi++) {
                int row = wm * 32 + mi * 16 + g;
                uint2 p0 = *(const uint2*)&as[row * ASTRIDE + ks + 2 * t];
                uint2 p1 = *(const uint2*)&as[(row + 8) * ASTRIDE + ks + 2 * t];
                af[mi][0] = p0.x; af[mi][1] = p1.x;
                af[mi][2] = p0.y; af[mi][3] = p1.y;
            }
            uint32_t bf[8][2];
#pragma unroll
            for (int ni = 0; ni < 8; ni++) {
                int nn = wn * 64 + ni * 8 + g;
                uint2 q = *(const uint2*)&bs[nn * ASTRIDE + ks + 2 * t];
                bf[ni][0] = q.x; bf[ni][1] = q.y;
            }
#pragma unroll
            for (int mi = 0; mi < 2; mi++)
#pragma unroll
                for (int ni = 0; ni < 8; ni++)
                    mma8(acc[mi][ni][0], acc[mi][ni][1], acc[mi][ni][2], acc[mi][ni][3],
                         af[mi][0], af[mi][1], af[mi][2], af[mi][3],
                         bf[ni][0], bf[ni][1]);
        }

        // ---- store prefetched tile into other buffer ----
        if (nxt) {
            uint32_t* asn = As[buf ^ 1];
            uint32_t* bsn = Bs[buf ^ 1];
#pragma unroll
            for (int i = 0; i < 2; i++) {
                int r = lr + i * 64;
                uint32_t* d = &asn[r * ASTRIDE + wbase];
                d[0] = f2tf(ra[i].x); d[2] = f2tf(ra[i].y);
                d[4] = f2tf(ra[i].z); d[6] = f2tf(ra[i].w);
                uint32_t* e = &bsn[r * ASTRIDE + wbase];
                e[0] = f2tf(rb[i].x); e[2] = f2tf(rb[i].y);
                e[4] = f2tf(rb[i].z); e[6] = f2tf(rb[i].w);
            }
        }
        __syncthreads();
        buf ^= 1;
    }

    // ---- epilogue ----
#pragma unroll
    for (int mi = 0; mi < 2; mi++) {
#pragma unroll
        for (int rr = 0; rr < 2; rr++) {
            int m = m0 + wm * 32 + mi * 16 + g + rr * 8;
#pragma unroll
            for (int ni = 0; ni < 8; ni++) {
                int n = n0 + wn * 64 + ni * 8 + 2 * t;
                float v0 = acc[mi][ni][rr * 2 + 0];
                float v1 = acc[mi][ni][rr * 2 + 1];
                if (HAS_BIAS) { v0 += bias[n]; v1 += bias[n + 1]; }
                if (RND) {
                    v0 = __uint_as_float(f2tf(v0));
                    v1 = __uint_as_float(f2tf(v1));
                }
                *(float2*)(C + (size_t)m * ldc + n) = make_float2(v0, v1);
            }
        }
    }
}

// ---------------------------------------------------------------------------
// Mask scan: set g_mask_allones=0 if any mask element is zero.
// ---------------------------------------------------------------------------
__global__ void mask_reset() { g_mask_allones = 1; }

__global__ void __launch_bounds__(512)
mask_scan(const int* __restrict__ mask)
{
    const int n4 = (SLEN * TLEN) / 4;
    int i = blockIdx.x * 512 + threadIdx.x;
    int bad = 0;
    for (; i < n4; i += gridDim.x * 512) {
        int4 v = ((const int4*)mask)[i];
        if (!(v.x && v.y && v.z && v.w)) bad = 1;
    }
    if (bad) g_mask_allones = 0;
}

// ---------------------------------------------------------------------------
// Fused flash attention: per CTA 128 query rows; stream K/V in T-tiles of 64.
// 512 threads = 16 warps: wm=warp>>1 (16 rows each), wn=warp&1.
// ---------------------------------------------------------------------------
#define BT 64
#define LDQ 132
#define LDK 132
#define LDV 136
#define LDP 68
#define OFF_Q 0
#define OFF_K 16896
#define OFF_V 25344
#define VBUFW 8704
#define OFF_P 42752
#define OFF_RM 51456
#define OFF_RS 51712
#define SMEM_WORDS 51968

__global__ void __launch_bounds__(512, 1)
attn_fused(const float* __restrict__ Q, const float* __restrict__ K,
           const float* __restrict__ V, const int* __restrict__ mask,
           float* __restrict__ AO)
{
    extern __shared__ uint32_t sm[];
    const uint32_t smb = smem_u32(sm);

    const int tid  = threadIdx.x;
    const int lane = tid & 31;
    const int warp = tid >> 5;       // 0..15
    const int wm   = warp >> 1;      // 0..7
    const int wn   = warp & 1;       // 0..1
    const int g    = lane >> 2;
    const int t    = lane & 3;
    const int s0   = blockIdx.x * 128;
    const int bh   = blockIdx.y;
    const int zn   = bh >> 4, zh = bh & 15;
    const float scale = 0.08838834764831845f;
    const bool use_mask = (g_mask_allones == 0);

    const size_t qbase  = ((size_t)zn * SLEN + s0) * EDIM + (size_t)zh * DHEAD;
    const size_t kvbase = ((size_t)zn * TLEN) * EDIM + (size_t)zh * DHEAD;

#pragma unroll
    for (int i = 0; i < 8; i++) {
        int idx = tid + i * 512;
        int r = idx >> 5, c = (idx & 31) << 2;
        cp16(smb + (OFF_Q + r * LDQ + c) * 4, Q + qbase + (size_t)r * EDIM + c);
    }
#pragma unroll
    for (int i = 0; i < 4; i++) {
        int idx = tid + i * 512;
        int r = idx >> 5, c = (idx & 31) << 2;
        cp16(smb + (OFF_K + r * LDK + c) * 4, K + kvbase + (size_t)r * EDIM + c);
    }
#pragma unroll
    for (int i = 0; i < 4; i++) {
        int idx = tid + i * 512;
        int r = idx >> 5, c = (idx & 31) << 2;
        cp16(smb + (OFF_V + r * LDV + c) * 4, V + kvbase + (size_t)r * EDIM + c);
    }
    asm volatile("cp.async.commit_group;");

    float Oa[8][4];
#pragma unroll
    for (int j = 0; j < 8; j++)
#pragma unroll
        for (int q = 0; q < 4; q++) Oa[j][q] = 0.0f;
    float m_run[2], l_run[2];
#pragma unroll
    for (int s = 0; s < 2; s++) { m_run[s] = NEG_INF; l_run[s] = 0.0f; }

    const int arow0 = wm * 16;

    for (int j = 0; j < TLEN / BT; j++) {
        asm volatile("cp.async.wait_group 0;" ::: "memory");
        __syncthreads();
        const int vb = j & 1;
        const int t0 = j * BT;

        float Sa[4][4];
#pragma unroll
        for (int n = 0; n < 4; n++)
#pragma unroll
            for (int q = 0; q < 4; q++) Sa[n][q] = 0.0f;

#pragma unroll
        for (int ks = 0; ks < DHEAD; ks += 8) {
            uint32_t af[4];
            {
                int row = arow0 + g;
                af[0] = sm[OFF_Q + row * LDQ + ks + t];
                af[1] = sm[OFF_Q + (row + 8) * LDQ + ks + t];
                af[2] = sm[OFF_Q + row * LDQ + ks + t + 4];
                af[3] = sm[OFF_Q + (row + 8) * LDQ + ks + t + 4];
            }
            uint32_t bf[4][2];
#pragma unroll
            for (int ni = 0; ni < 4; ni++) {
                int n = wn * 32 + ni * 8 + g;
                bf[ni][0] = sm[OFF_K + n * LDK + ks + t];
                bf[ni][1] = sm[OFF_K + n * LDK + ks + t + 4];
            }
#pragma unroll
            for (int ni = 0; ni < 4; ni++)
                mma8(Sa[ni][0], Sa[ni][1], Sa[ni][2], Sa[ni][3],
                     af[0], af[1], af[2], af[3], bf[ni][0], bf[ni][1]);
        }

#pragma unroll
        for (int ni = 0; ni < 4; ni++)
#pragma unroll
            for (int q = 0; q < 4; q++) Sa[ni][q] *= scale;

        if (use_mask) {
#pragma unroll
            for (int rr = 0; rr < 2; rr++) {
                int srow = s0 + arow0 + rr * 8 + g;
#pragma unroll
                for (int ni = 0; ni < 4; ni++)
#pragma unroll
                    for (int q = 0; q < 2; q++) {
                        int col = t0 + wn * 32 + ni * 8 + 2 * t + q;
                        if (__ldg(&mask[(size_t)col * SLEN + srow]) == 0)
                            Sa[ni][rr * 2 + q] = NEG_INF;
                    }
            }
        }

#pragma unroll
        for (int rr = 0; rr < 2; rr++) {
            float mx = NEG_INF;
#pragma unroll
            for (int ni = 0; ni < 4; ni++) {
                mx = fmaxf(mx, Sa[ni][rr * 2]);
                mx = fmaxf(mx, Sa[ni][rr * 2 + 1]);
            }
            mx = fmaxf(mx, __shfl_xor_sync(0xffffffffu, mx, 1));
            mx = fmaxf(mx, __shfl_xor_sync(0xffffffffu, mx, 2));
            if (t == 0) {
                int r = arow0 + rr * 8 + g;
                *(float*)&sm[OFF_RM + r * 2 + wn] = mx;
            }
        }
        __syncthreads();

        float m_new[2], alpha[2];
#pragma unroll
        for (int rr = 0; rr < 2; rr++) {
            int r = arow0 + rr * 8 + g;
            float tm = fmaxf(*(float*)&sm[OFF_RM + r * 2],
                             *(float*)&sm[OFF_RM + r * 2 + 1]);
            m_new[rr] = fmaxf(m_run[rr], tm);
            alpha[rr] = __expf(m_run[rr] - m_new[rr]);
            m_run[rr] = m_new[rr];
        }

#pragma unroll
        for (int rr = 0; rr < 2; rr++) {
            int r = arow0 + rr * 8 + g;
            float sum = 0.0f;
#pragma unroll
            for (int ni = 0; ni < 4; ni++) {
                float p0 = __expf(Sa[ni][rr * 2]     - m_new[rr]);
                float p1 = __expf(Sa[ni][rr * 2 + 1] - m_new[rr]);
                sum += p0 + p1;
                uint2 pp = make_uint2(f2tf(p0), f2tf(p1));
                *(uint2*)&sm[OFF_P + r * LDP + wn * 32 + ni * 8 + 2 * t] = pp;
            }
            sum += __shfl_xor_sync(0xffffffffu, sum, 1);
            sum += __shfl_xor_sync(0xffffffffu, sum, 2);
            if (t == 0) *(float*)&sm[OFF_RS + r * 2 + wn] = sum;
        }
        __syncthreads();

#pragma unroll
        for (int rr = 0; rr < 2; rr++) {
            int r = arow0 + rr * 8 + g;
            float ts = *(float*)&sm[OFF_RS + r * 2] + *(float*)&sm[OFF_RS + r * 2 + 1];
            l_run[rr] = l_run[rr] * alpha[rr] + ts;
        }
#pragma unroll
        for (int ni = 0; ni < 8; ni++)
#pragma unroll
            for (int q = 0; q < 4; q++)
                Oa[ni][q] *= alpha[q >> 1];

        if (j + 1 < TLEN / BT) {
            const int tn = (j + 1) * BT;
            const int vn = vb ^ 1;
#pragma unroll
            for (int i = 0; i < 4; i++) {
                int idx = tid + i * 512;
                int r = idx >> 5, c = (idx & 31) << 2;
                cp16(smb + (OFF_K + r * LDK + c) * 4,
                     K + kvbase + (size_t)(tn + r) * EDIM + c);
            }
#pragma unroll
            for (int i = 0; i < 4; i++) {
                int idx = tid + i * 512;
                int r = idx >> 5, c = (idx & 31) << 2;
                cp16(smb + (OFF_V + vn * VBUFW + r * LDV + c) * 4,
                     V + kvbase + (size_t)(tn + r) * EDIM + c);
            }
            asm volatile("cp.async.commit_group;");
        }

        const uint32_t* vs = &sm[OFF_V + vb * VBUFW];
#pragma unroll
        for (int ks = 0; ks < BT; ks += 8) {
            uint32_t af[4];
            {
                int row = arow0 + g;
                af[0] = sm[OFF_P + row * LDP + ks + t];
                af[1] = sm[OFF_P + (row + 8) * LDP + ks + t];
                af[2] = sm[OFF_P + row * LDP + ks + t + 4];
                af[3] = sm[OFF_P + (row + 8) * LDP + ks + t + 4];
            }
            uint32_t bf[8][2];
#pragma unroll
            for (int ni = 0; ni < 8; ni++) {
                int n = wn * 64 + ni * 8 + g;
                bf[ni][0] = vs[(ks + t) * LDV + n];
                bf[ni][1] = vs[(ks + t + 4) * LDV + n];
            }
#pragma unroll
            for (int ni = 0; ni < 8; ni++)
                mma8(Oa[ni][0], Oa[ni][1], Oa[ni][2], Oa[ni][3],
                     af[0], af[1], af[2], af[3], bf[ni][0], bf[ni][1]);
        }
    }

#pragma unroll
    for (int rr = 0; rr < 2; rr++) {
        float inv = 1.0f / l_run[rr];
        int r = arow0 + rr * 8 + g;
#pragma unroll
        for (int ni = 0; ni < 8; ni++) {
            int col = wn * 64 + ni * 8 + 2 * t;
            float2 o = make_float2(
                __uint_as_float(f2tf(Oa[ni][rr * 2] * inv)),
                __uint_as_float(f2tf(Oa[ni][rr * 2 + 1] * inv)));
            *(float2*)(AO + qbase + (size_t)r * EDIM + col) = o;
        }
    }
}

// ---------------------------------------------------------------------------
// Host launcher
// ---------------------------------------------------------------------------
extern "C" void kernel_launch(void* const* d_in, const int* in_sizes, int n_in,
                              void* d_out, int out_size)
{
    const float* query = (const float*)d_in[0];
    const float* key   = (const float*)d_in[1];
    const float* value = (const float*)d_in[2];
    const int*   amask = (const int*)  d_in[3];
    const float* Wq    = (const float*)d_in[4];
    const float* bq    = (const float*)d_in[5];
    const float* Wk    = (const float*)d_in[6];
    const float* bk    = (const float*)d_in[7];
    const float* Wv    = (const float*)d_in[8];
    const float* bv    = (const float*)d_in[9];
    const float* Wp    = (const float*)d_in[10];
    const float* bp    = (const float*)d_in[11];
    float* out = (float*)d_out;

    float *Qp, *Kp, *Vp, *AOp;
    cudaGetSymbolAddress((void**)&Qp,  g_Q);
    cudaGetSymbolAddress((void**)&Kp,  g_K);
    cudaGetSymbolAddress((void**)&Vp,  g_V);
    cudaGetSymbolAddress((void**)&AOp, g_AO);

    const int M = NB * SLEN;   // 8192

    dim3 blk(256);
    dim3 gProj(EDIM / 128, M / 128, 1);          // 16 x 64

    cudaFuncSetAttribute(attn_fused,
                         cudaFuncAttributeMaxDynamicSharedMemorySize, SMEM_WORDS * 4);

    // 0) mask all-ones scan
    mask_reset<<<1, 1>>>();
    mask_scan<<<1024, 512>>>(amask);

    // 1-3) Q, K, V projections (outputs tf32-rounded)
    gemm_tc<true, true><<<gProj, blk>>>(query, EDIM, Wq, EDIM, Qp, EDIM, bq, EDIM);
    gemm_tc<true, true><<<gProj, blk>>>(key,   EDIM, Wk, EDIM, Kp, EDIM, bk, EDIM);
    gemm_tc<true, true><<<gProj, blk>>>(value, EDIM, Wv, EDIM, Vp, EDIM, bv, EDIM);

    // 4) fused attention (512 threads, 16 warps)
    {
        dim3 g(SLEN / 128, NB * HNUM);
        attn_fused<<<g, dim3(512), SMEM_WORDS * 4>>>(Qp, Kp, Vp, amask, AOp);
    }

    // 5) output projection (full fp32 store)
    gemm_tc<true, false><<<gProj, blk>>>(AOp, EDIM, Wp, EDIM, out, EDIM, bp, EDIM);
}

// round 13
// speedup vs baseline: 2.5725x; 2.5725x over previous
#include <cuda_runtime.h>
#include <cuda_fp16.h>
#include <cstdint>

// Problem constants
#define EDIM 2048
#define HNUM 16
#define NB   4
#define SLEN 2048
#define TLEN 2048
#define DHEAD 128

#define NEG_INF (__int_as_float(0xff800000))

// Scratch (allocation-free rule: __device__ globals)
__device__ float g_Q [(size_t)NB * SLEN * EDIM];            // 64 MB (tf32-rounded)
__device__ float g_K [(size_t)NB * TLEN * EDIM];            // 64 MB (tf32-rounded)
__device__ float g_V [(size_t)NB * TLEN * EDIM];            // 64 MB (tf32-rounded)
__device__ float g_AO[(size_t)NB * SLEN * EDIM];            // 64 MB (tf32-rounded)
__device__ int   g_mask_allones;

// fp32 -> tf32 round-to-nearest
__device__ __forceinline__ uint32_t f2tf(float f) {
    uint32_t u;
    asm("cvt.rna.tf32.f32 %0, %1;" : "=r"(u) : "f"(f));
    return u;
}
// pack two fp32 -> half2 (round-to-nearest)
__device__ __forceinline__ uint32_t pkh2(float x, float y) {
    __half2 h = __floats2half2_rn(x, y);
    return *(uint32_t*)&h;
}

// tf32 m16n8k8 (used by fused attention)
__device__ __forceinline__ void mma8(float& c0, float& c1, float& c2, float& c3,
                                     uint32_t a0, uint32_t a1, uint32_t a2, uint32_t a3,
                                     uint32_t b0, uint32_t b1) {
    asm volatile(
        "mma.sync.aligned.m16n8k8.row.col.f32.tf32.tf32.f32 "
        "{%0,%1,%2,%3},{%4,%5,%6,%7},{%8,%9},{%0,%1,%2,%3};"
        : "+f"(c0), "+f"(c1), "+f"(c2), "+f"(c3)
        : "r"(a0), "r"(a1), "r"(a2), "r"(a3), "r"(b0), "r"(b1));
}

// fp16 m16n8k16 with fp32 accumulate (projection GEMMs)
__device__ __forceinline__ void mma16(float& c0, float& c1, float& c2, float& c3,
                                      uint32_t a0, uint32_t a1, uint32_t a2, uint32_t a3,
                                      uint32_t b0, uint32_t b1) {
    asm volatile(
        "mma.sync.aligned.m16n8k16.row.col.f32.f16.f16.f32 "
        "{%0,%1,%2,%3},{%4,%5,%6,%7},{%8,%9},{%0,%1,%2,%3};"
        : "+f"(c0), "+f"(c1), "+f"(c2), "+f"(c3)
        : "r"(a0), "r"(a1), "r"(a2), "r"(a3), "r"(b0), "r"(b1));
}

__device__ __forceinline__ uint32_t smem_u32(const void* p) {
    uint32_t a;
    asm("{ .reg .u64 t; cvta.to.shared.u64 t, %1; cvt.u32.u64 %0, t; }" : "=r"(a) : "l"(p));
    return a;
}
__device__ __forceinline__ void cp16(uint32_t dst, const void* src) {
    asm volatile("cp.async.cg.shared.global [%0], [%1], 16;" :: "r"(dst), "l"(src));
}

// ---------------------------------------------------------------------------
// fp16 tensor-core GEMM (TRANSB form): C[m][n] = sum_k A[m][k]*B[n][k]
// 128x128 CTA tile, kChunk=16, 256 threads, register-double-buffered SMEM.
// SMEM rows hold 8 half2 words (16 halves) at stride HSTR=12 words:
//   12g mod 32 = {0,12,24,4,16,28,8,20}, +t -> all 32 banks, conflict-free.
// fp32 accumulate; bias fp32; RND: round stored C to tf32.
// ---------------------------------------------------------------------------
#define HSTR 12

template<bool HAS_BIAS, bool RND>
__global__ void __launch_bounds__(256, 2)
gemm_tc(const float* __restrict__ A, int lda,
        const float* __restrict__ B, int ldb,
        float*       __restrict__ C, int ldc,
        const float* __restrict__ bias, int K)
{
    __shared__ uint32_t As[2][128 * HSTR];
    __shared__ uint32_t Bs[2][128 * HSTR];

    const int tid  = threadIdx.x;
    const int lane = tid & 31;
    const int warp = tid >> 5;
    const int wm   = warp & 3;
    const int wn   = warp >> 2;
    const int m0   = blockIdx.y * 128;
    const int n0   = blockIdx.x * 128;

    const int lr = tid >> 2;           // 0..63
    const int lk = (tid & 3) << 2;     // 0,4,8,12 (fp32 k offset)
    const int lw = lk >> 1;            // 0,2,4,6  (half2 word offset)
    const int g  = lane >> 2;
    const int t  = lane & 3;

    float acc[2][8][4];
#pragma unroll
    for (int i = 0; i < 2; i++)
#pragma unroll
        for (int j = 0; j < 8; j++)
#pragma unroll
            for (int q = 0; q < 4; q++) acc[i][j][q] = 0.0f;

    const int nch = K >> 4;

    // ---- initial tile load (chunk 0) ----
#pragma unroll
    for (int i = 0; i < 2; i++) {
        int r = lr + i * 64;
        float4 v = *(const float4*)(A + (size_t)(m0 + r) * lda + lk);
        *(uint2*)&As[0][r * HSTR + lw] = make_uint2(pkh2(v.x, v.y), pkh2(v.z, v.w));
        float4 w = *(const float4*)(B + (size_t)(n0 + r) * ldb + lk);
        *(uint2*)&Bs[0][r * HSTR + lw] = make_uint2(pkh2(w.x, w.y), pkh2(w.z, w.w));
    }
    __syncthreads();

    int buf = 0;
    for (int ch = 0; ch < nch; ch++) {
        const bool nxt = (ch + 1 < nch);
        const int  k1  = (ch + 1) << 4;

        float4 ra[2], rb[2];
        if (nxt) {
#pragma unroll
            for (int i = 0; i < 2; i++) {
                int r = lr + i * 64;
                ra[i] = *(const float4*)(A + (size_t)(m0 + r) * lda + k1 + lk);
                rb[i] = *(const float4*)(B + (size_t)(n0 + r) * ldb + k1 + lk);
            }
        }

        // ---- compute on current buffer: one m16n8k16 per (mi, ni) ----
        const uint32_t* as = As[buf];
        const uint32_t* bs = Bs[buf];
        {
            uint32_t af[2][4];
#pragma unroll
            for (int mi = 0; mi < 2; mi++) {
                int row = wm * 32 + mi * 16 + g;
                af[mi][0] = as[row * HSTR + t];
                af[mi][1] = as[(row + 8) * HSTR + t];
                af[mi][2] = as[row * HSTR + t + 4];
                af[mi][3] = as[(row + 8) * HSTR + t + 4];
            }
            uint32_t bf[8][2];
#pragma unroll
            for (int ni = 0; ni < 8; ni++) {
                int nn = wn * 64 + ni * 8 + g;
                bf[ni][0] = bs[nn * HSTR + t];
                bf[ni][1] = bs[nn * HSTR + t + 4];
            }
#pragma unroll
            for (int mi = 0; mi < 2; mi++)
#pragma unroll
                for (int ni = 0; ni < 8; ni++)
                    mma16(acc[mi][ni][0], acc[mi][ni][1], acc[mi][ni][2], acc[mi][ni][3],
                          af[mi][0], af[mi][1], af[mi][2], af[mi][3],
                          bf[ni][0], bf[ni][1]);
        }

        // ---- store prefetched tile into other buffer ----
        if (nxt) {
            uint32_t* asn = As[buf ^ 1];
            uint32_t* bsn = Bs[buf ^ 1];
#pragma unroll
            for (int i = 0; i < 2; i++) {
                int r = lr + i * 64;
                *(uint2*)&asn[r * HSTR + lw] =
                    make_uint2(pkh2(ra[i].x, ra[i].y), pkh2(ra[i].z, ra[i].w));
                *(uint2*)&bsn[r * HSTR + lw] =
                    make_uint2(pkh2(rb[i].x, rb[i].y), pkh2(rb[i].z, rb[i].w));
            }
        }
        __syncthreads();
        buf ^= 1;
    }

    // ---- epilogue ----
#pragma unroll
    for (int mi = 0; mi < 2; mi++) {
#pragma unroll
        for (int rr = 0; rr < 2; rr++) {
            int m = m0 + wm * 32 + mi * 16 + g + rr * 8;
#pragma unroll
            for (int ni = 0; ni < 8; ni++) {
                int n = n0 + wn * 64 + ni * 8 + 2 * t;
                float v0 = acc[mi][ni][rr * 2 + 0];
                float v1 = acc[mi][ni][rr * 2 + 1];
                if (HAS_BIAS) { v0 += bias[n]; v1 += bias[n + 1]; }
                if (RND) {
                    v0 = __uint_as_float(f2tf(v0));
                    v1 = __uint_as_float(f2tf(v1));
                }
                *(float2*)(C + (size_t)m * ldc + n) = make_float2(v0, v1);
            }
        }
    }
}

// ---------------------------------------------------------------------------
// Mask scan: set g_mask_allones=0 if any mask element is zero.
// ---------------------------------------------------------------------------
__global__ void mask_reset() { g_mask_allones = 1; }

__global__ void __launch_bounds__(512)
mask_scan(const int* __restrict__ mask)
{
    const int n4 = (SLEN * TLEN) / 4;
    int i = blockIdx.x * 512 + threadIdx.x;
    int bad = 0;
    for (; i < n4; i += gridDim.x * 512) {
        int4 v = ((const int4*)mask)[i];
        if (!(v.x && v.y && v.z && v.w)) bad = 1;
    }
    if (bad) g_mask_allones = 0;
}

// ---------------------------------------------------------------------------
// Fused flash attention (round-8 baseline, unchanged): per CTA 128 query rows;
// stream K/V in T-tiles of 64. 512 threads = 16 warps.
// ---------------------------------------------------------------------------
#define BT 64
#define LDQ 132
#define LDK 132
#define LDV 136
#define LDP 68
#define OFF_Q 0
#define OFF_K 16896
#define OFF_V 25344
#define VBUFW 8704
#define OFF_P 42752
#define OFF_RM 51456
#define OFF_RS 51712
#define SMEM_WORDS 51968

__global__ void __launch_bounds__(512, 1)
attn_fused(const float* __restrict__ Q, const float* __restrict__ K,
           const float* __restrict__ V, const int* __restrict__ mask,
           float* __restrict__ AO)
{
    extern __shared__ uint32_t sm[];
    const uint32_t smb = smem_u32(sm);

    const int tid  = threadIdx.x;
    const int lane = tid & 31;
    const int warp = tid >> 5;       // 0..15
    const int wm   = warp >> 1;      // 0..7
    const int wn   = warp & 1;       // 0..1
    const int g    = lane >> 2;
    const int t    = lane & 3;
    const int s0   = blockIdx.x * 128;
    const int bh   = blockIdx.y;
    const int zn   = bh >> 4, zh = bh & 15;
    const float scale = 0.08838834764831845f;
    const bool use_mask = (g_mask_allones == 0);

    const size_t qbase  = ((size_t)zn * SLEN + s0) * EDIM + (size_t)zh * DHEAD;
    const size_t kvbase = ((size_t)zn * TLEN) * EDIM + (size_t)zh * DHEAD;

#pragma unroll
    for (int i = 0; i < 8; i++) {
        int idx = tid + i * 512;
        int r = idx >> 5, c = (idx & 31) << 2;
        cp16(smb + (OFF_Q + r * LDQ + c) * 4, Q + qbase + (size_t)r * EDIM + c);
    }
#pragma unroll
    for (int i = 0; i < 4; i++) {
        int idx = tid + i * 512;
        int r = idx >> 5, c = (idx & 31) << 2;
        cp16(smb + (OFF_K + r * LDK + c) * 4, K + kvbase + (size_t)r * EDIM + c);
    }
#pragma unroll
    for (int i = 0; i < 4; i++) {
        int idx = tid + i * 512;
        int r = idx >> 5, c = (idx & 31) << 2;
        cp16(smb + (OFF_V + r * LDV + c) * 4, V + kvbase + (size_t)r * EDIM + c);
    }
    asm volatile("cp.async.commit_group;");

    float Oa[8][4];
#pragma unroll
    for (int j = 0; j < 8; j++)
#pragma unroll
        for (int q = 0; q < 4; q++) Oa[j][q] = 0.0f;
    float m_run[2], l_run[2];
#pragma unroll
    for (int s = 0; s < 2; s++) { m_run[s] = NEG_INF; l_run[s] = 0.0f; }

    const int arow0 = wm * 16;

    for (int j = 0; j < TLEN / BT; j++) {
        asm volatile("cp.async.wait_group 0;" ::: "memory");
        __syncthreads();
        const int vb = j & 1;
        const int t0 = j * BT;

        float Sa[4][4];
#pragma unroll
        for (int n = 0; n < 4; n++)
#pragma unroll
            for (int q = 0; q < 4; q++) Sa[n][q] = 0.0f;

#pragma unroll
        for (int ks = 0; ks < DHEAD; ks += 8) {
            uint32_t af[4];
            {
                int row = arow0 + g;
                af[0] = sm[OFF_Q + row * LDQ + ks + t];
                af[1] = sm[OFF_Q + (row + 8) * LDQ + ks + t];
                af[2] = sm[OFF_Q + row * LDQ + ks + t + 4];
                af[3] = sm[OFF_Q + (row + 8) * LDQ + ks + t + 4];
            }
            uint32_t bf[4][2];
#pragma unroll
            for (int ni = 0; ni < 4; ni++) {
                int n = wn * 32 + ni * 8 + g;
                bf[ni][0] = sm[OFF_K + n * LDK + ks + t];
                bf[ni][1] = sm[OFF_K + n * LDK + ks + t + 4];
            }
#pragma unroll
            for (int ni = 0; ni < 4; ni++)
                mma8(Sa[ni][0], Sa[ni][1], Sa[ni][2], Sa[ni][3],
                     af[0], af[1], af[2], af[3], bf[ni][0], bf[ni][1]);
        }

#pragma unroll
        for (int ni = 0; ni < 4; ni++)
#pragma unroll
            for (int q = 0; q < 4; q++) Sa[ni][q] *= scale;

        if (use_mask) {
#pragma unroll
            for (int rr = 0; rr < 2; rr++) {
                int srow = s0 + arow0 + rr * 8 + g;
#pragma unroll
                for (int ni = 0; ni < 4; ni++)
#pragma unroll
                    for (int q = 0; q < 2; q++) {
                        int col = t0 + wn * 32 + ni * 8 + 2 * t + q;
                        if (__ldg(&mask[(size_t)col * SLEN + srow]) == 0)
                            Sa[ni][rr * 2 + q] = NEG_INF;
                    }
            }
        }

#pragma unroll
        for (int rr = 0; rr < 2; rr++) {
            float mx = NEG_INF;
#pragma unroll
            for (int ni = 0; ni < 4; ni++) {
                mx = fmaxf(mx, Sa[ni][rr * 2]);
                mx = fmaxf(mx, Sa[ni][rr * 2 + 1]);
            }
            mx = fmaxf(mx, __shfl_xor_sync(0xffffffffu, mx, 1));
            mx = fmaxf(mx, __shfl_xor_sync(0xffffffffu, mx, 2));
            if (t == 0) {
                int r = arow0 + rr * 8 + g;
                *(float*)&sm[OFF_RM + r * 2 + wn] = mx;
            }
        }
        __syncthreads();

        float m_new[2], alpha[2];
#pragma unroll
        for (int rr = 0; rr < 2; rr++) {
            int r = arow0 + rr * 8 + g;
            float tm = fmaxf(*(float*)&sm[OFF_RM + r * 2],
                             *(float*)&sm[OFF_RM + r * 2 + 1]);
            m_new[rr] = fmaxf(m_run[rr], tm);
            alpha[rr] = __expf(m_run[rr] - m_new[rr]);
            m_run[rr] = m_new[rr];
        }

#pragma unroll
        for (int rr = 0; rr < 2; rr++) {
            int r = arow0 + rr * 8 + g;
            float sum = 0.0f;
#pragma unroll
            for (int ni = 0; ni < 4; ni++) {
                float p0 = __expf(Sa[ni][rr * 2]     - m_new[rr]);
                float p1 = __expf(Sa[ni][rr * 2 + 1] - m_new[rr]);
                sum += p0 + p1;
                uint2 pp = make_uint2(f2tf(p0), f2tf(p1));
                *(uint2*)&sm[OFF_P + r * LDP + wn * 32 + ni * 8 + 2 * t] = pp;
            }
            sum += __shfl_xor_sync(0xffffffffu, sum, 1);
            sum += __shfl_xor_sync(0xffffffffu, sum, 2);
            if (t == 0) *(float*)&sm[OFF_RS + r * 2 + wn] = sum;
        }
        __syncthreads();

#pragma unroll
        for (int rr = 0; rr < 2; rr++) {
            int r = arow0 + rr * 8 + g;
            float ts = *(float*)&sm[OFF_RS + r * 2] + *(float*)&sm[OFF_RS + r * 2 + 1];
            l_run[rr] = l_run[rr] * alpha[rr] + ts;
        }
#pragma unroll
        for (int ni = 0; ni < 8; ni++)
#pragma unroll
            for (int q = 0; q < 4; q++)
                Oa[ni][q] *= alpha[q >> 1];

        if (j + 1 < TLEN / BT) {
            const int tn = (j + 1) * BT;
            const int vn = vb ^ 1;
#pragma unroll
            for (int i = 0; i < 4; i++) {
                int idx = tid + i * 512;
                int r = idx >> 5, c = (idx & 31) << 2;
                cp16(smb + (OFF_K + r * LDK + c) * 4,
                     K + kvbase + (size_t)(tn + r) * EDIM + c);
            }
#pragma unroll
            for (int i = 0; i < 4; i++) {
                int idx = tid + i * 512;
                int r = idx >> 5, c = (idx & 31) << 2;
                cp16(smb + (OFF_V + vn * VBUFW + r * LDV + c) * 4,
                     V + kvbase + (size_t)(tn + r) * EDIM + c);
            }
            asm volatile("cp.async.commit_group;");
        }

        const uint32_t* vs = &sm[OFF_V + vb * VBUFW];
#pragma unroll
        for (int ks = 0; ks < BT; ks += 8) {
            uint32_t af[4];
            {
                int row = arow0 + g;
                af[0] = sm[OFF_P + row * LDP + ks + t];
                af[1] = sm[OFF_P + (row + 8) * LDP + ks + t];
                af[2] = sm[OFF_P + row * LDP + ks + t + 4];
                af[3] = sm[OFF_P + (row + 8) * LDP + ks + t + 4];
            }
            uint32_t bf[8][2];
#pragma unroll
            for (int ni = 0; ni < 8; ni++) {
                int n = wn * 64 + ni * 8 + g;
                bf[ni][0] = vs[(ks + t) * LDV + n];
                bf[ni][1] = vs[(ks + t + 4) * LDV + n];
            }
#pragma unroll
            for (int ni = 0; ni < 8; ni++)
                mma8(Oa[ni][0], Oa[ni][1], Oa[ni][2], Oa[ni][3],
                     af[0], af[1], af[2], af[3], bf[ni][0], bf[ni][1]);
        }
    }

#pragma unroll
    for (int rr = 0; rr < 2; rr++) {
        float inv = 1.0f / l_run[rr];
        int r = arow0 + rr * 8 + g;
#pragma unroll
        for (int ni = 0; ni < 8; ni++) {
            int col = wn * 64 + ni * 8 + 2 * t;
            float2 o = make_float2(
                __uint_as_float(f2tf(Oa[ni][rr * 2] * inv)),
                __uint_as_float(f2tf(Oa[ni][rr * 2 + 1] * inv)));
            *(float2*)(AO + qbase + (size_t)r * EDIM + col) = o;
        }
    }
}

// ---------------------------------------------------------------------------
// Host launcher
// ---------------------------------------------------------------------------
extern "C" void kernel_launch(void* const* d_in, const int* in_sizes, int n_in,
                              void* d_out, int out_size)
{
    const float* query = (const float*)d_in[0];
    const float* key   = (const float*)d_in[1];
    const float* value = (const float*)d_in[2];
    const int*   amask = (const int*)  d_in[3];
    const float* Wq    = (const float*)d_in[4];
    const float* bq    = (const float*)d_in[5];
    const float* Wk    = (const float*)d_in[6];
    const float* bk    = (const float*)d_in[7];
    const float* Wv    = (const float*)d_in[8];
    const float* bv    = (const float*)d_in[9];
    const float* Wp    = (const float*)d_in[10];
    const float* bp    = (const float*)d_in[11];
    float* out = (float*)d_out;

    float *Qp, *Kp, *Vp, *AOp;
    cudaGetSymbolAddress((void**)&Qp,  g_Q);
    cudaGetSymbolAddress((void**)&Kp,  g_K);
    cudaGetSymbolAddress((void**)&Vp,  g_V);
    cudaGetSymbolAddress((void**)&AOp, g_AO);

    const int M = NB * SLEN;   // 8192

    dim3 blk(256);
    dim3 gProj(EDIM / 128, M / 128, 1);          // 16 x 64

    cudaFuncSetAttribute(attn_fused,
                         cudaFuncAttributeMaxDynamicSharedMemorySize, SMEM_WORDS * 4);

    // 0) mask all-ones scan
    mask_reset<<<1, 1>>>();
    mask_scan<<<1024, 512>>>(amask);

    // 1-3) Q, K, V projections in fp16 (outputs tf32-rounded fp32)
    gemm_tc<true, true><<<gProj, blk>>>(query, EDIM, Wq, EDIM, Qp, EDIM, bq, EDIM);
    gemm_tc<true, true><<<gProj, blk>>>(key,   EDIM, Wk, EDIM, Kp, EDIM, bk, EDIM);
    gemm_tc<true, true><<<gProj, blk>>>(value, EDIM, Wv, EDIM, Vp, EDIM, bv, EDIM);

    // 4) fused attention (tf32, 512 threads)
    {
        dim3 g(SLEN / 128, NB * HNUM);
        attn_fused<<<g, dim3(512), SMEM_WORDS * 4>>>(Qp, Kp, Vp, amask, AOp);
    }

    // 5) output projection in fp16 (full fp32 store)
    gemm_tc<true, false><<<gProj, blk>>>(AOp, EDIM, Wp, EDIM, out, EDIM, bp, EDIM);
}

// round 15
// speedup vs baseline: 2.8474x; 1.1069x over previous
#include <cuda_runtime.h>
#include <cuda_fp16.h>
#include <cstdint>

// Problem constants
#define EDIM 2048
#define HNUM 16
#define NB   4
#define SLEN 2048
#define TLEN 2048
#define DHEAD 128

#define NEG_INF (__int_as_float(0xff800000))

// Scratch (allocation-free rule: __device__ globals)
__device__ __half g_Q [(size_t)NB * SLEN * EDIM];           // 32 MB fp16
__device__ __half g_K [(size_t)NB * TLEN * EDIM];           // 32 MB fp16
__device__ float  g_V [(size_t)NB * TLEN * EDIM];           // 64 MB (tf32-rounded)
__device__ float  g_AO[(size_t)NB * SLEN * EDIM];           // 64 MB (tf32-rounded)
__device__ int    g_mask_allones;

// fp32 -> tf32 round-to-nearest
__device__ __forceinline__ uint32_t f2tf(float f) {
    uint32_t u;
    asm("cvt.rna.tf32.f32 %0, %1;" : "=r"(u) : "f"(f));
    return u;
}
// pack two fp32 -> half2 (round-to-nearest)
__device__ __forceinline__ uint32_t pkh2(float x, float y) {
    __half2 h = __floats2half2_rn(x, y);
    return *(uint32_t*)&h;
}

// tf32 m16n8k8 (PV in fused attention)
__device__ __forceinline__ void mma8(float& c0, float& c1, float& c2, float& c3,
                                     uint32_t a0, uint32_t a1, uint32_t a2, uint32_t a3,
                                     uint32_t b0, uint32_t b1) {
    asm volatile(
        "mma.sync.aligned.m16n8k8.row.col.f32.tf32.tf32.f32 "
        "{%0,%1,%2,%3},{%4,%5,%6,%7},{%8,%9},{%0,%1,%2,%3};"
        : "+f"(c0), "+f"(c1), "+f"(c2), "+f"(c3)
        : "r"(a0), "r"(a1), "r"(a2), "r"(a3), "r"(b0), "r"(b1));
}

// fp16 m16n8k16 with fp32 accumulate (projections + QK^T)
__device__ __forceinline__ void mma16(float& c0, float& c1, float& c2, float& c3,
                                      uint32_t a0, uint32_t a1, uint32_t a2, uint32_t a3,
                                      uint32_t b0, uint32_t b1) {
    asm volatile(
        "mma.sync.aligned.m16n8k16.row.col.f32.f16.f16.f32 "
        "{%0,%1,%2,%3},{%4,%5,%6,%7},{%8,%9},{%0,%1,%2,%3};"
        : "+f"(c0), "+f"(c1), "+f"(c2), "+f"(c3)
        : "r"(a0), "r"(a1), "r"(a2), "r"(a3), "r"(b0), "r"(b1));
}

__device__ __forceinline__ uint32_t smem_u32(const void* p) {
    uint32_t a;
    asm("{ .reg .u64 t; cvta.to.shared.u64 t, %1; cvt.u32.u64 %0, t; }" : "=r"(a) : "l"(p));
    return a;
}
__device__ __forceinline__ void cp16(uint32_t dst, const void* src) {
    asm volatile("cp.async.cg.shared.global [%0], [%1], 16;" :: "r"(dst), "l"(src));
}

// ---------------------------------------------------------------------------
// fp16 tensor-core GEMM (TRANSB form): C[m][n] = sum_k A[m][k]*B[n][k]
// 128x128 CTA tile, kChunk=16, 256 threads, register-double-buffered SMEM.
// SMEM rows: 8 half2 words at stride HSTR=12 (conflict-free).
// OMODE: 0 = fp32 store, 1 = fp32 tf32-rounded store, 2 = fp16 store.
// ---------------------------------------------------------------------------
#define HSTR 12

template<bool HAS_BIAS, int OMODE>
__global__ void __launch_bounds__(256, 2)
gemm_tc(const float* __restrict__ A, int lda,
        const float* __restrict__ B, int ldb,
        void*        __restrict__ Cv, int ldc,
        const float* __restrict__ bias, int K)
{
    __shared__ uint32_t As[2][128 * HSTR];
    __shared__ uint32_t Bs[2][128 * HSTR];

    const int tid  = threadIdx.x;
    const int lane = tid & 31;
    const int warp = tid >> 5;
    const int wm   = warp & 3;
    const int wn   = warp >> 2;
    const int m0   = blockIdx.y * 128;
    const int n0   = blockIdx.x * 128;

    const int lr = tid >> 2;           // 0..63
    const int lk = (tid & 3) << 2;     // 0,4,8,12 (fp32 k offset)
    const int lw = lk >> 1;            // 0,2,4,6  (half2 word offset)
    const int g  = lane >> 2;
    const int t  = lane & 3;

    float acc[2][8][4];
#pragma unroll
    for (int i = 0; i < 2; i++)
#pragma unroll
        for (int j = 0; j < 8; j++)
#pragma unroll
            for (int q = 0; q < 4; q++) acc[i][j][q] = 0.0f;

    const int nch = K >> 4;

    // ---- initial tile load (chunk 0) ----
#pragma unroll
    for (int i = 0; i < 2; i++) {
        int r = lr + i * 64;
        float4 v = *(const float4*)(A + (size_t)(m0 + r) * lda + lk);
        *(uint2*)&As[0][r * HSTR + lw] = make_uint2(pkh2(v.x, v.y), pkh2(v.z, v.w));
        float4 w = *(const float4*)(B + (size_t)(n0 + r) * ldb + lk);
        *(uint2*)&Bs[0][r * HSTR + lw] = make_uint2(pkh2(w.x, w.y), pkh2(w.z, w.w));
    }
    __syncthreads();

    int buf = 0;
    for (int ch = 0; ch < nch; ch++) {
        const bool nxt = (ch + 1 < nch);
        const int  k1  = (ch + 1) << 4;

        float4 ra[2], rb[2];
        if (nxt) {
#pragma unroll
            for (int i = 0; i < 2; i++) {
                int r = lr + i * 64;
                ra[i] = *(const float4*)(A + (size_t)(m0 + r) * lda + k1 + lk);
                rb[i] = *(const float4*)(B + (size_t)(n0 + r) * ldb + k1 + lk);
            }
        }

        // ---- compute: one m16n8k16 per (mi, ni) ----
        const uint32_t* as = As[buf];
        const uint32_t* bs = Bs[buf];
        {
            uint32_t af[2][4];
#pragma unroll
            for (int mi = 0; mi < 2; mi++) {
                int row = wm * 32 + mi * 16 + g;
                af[mi][0] = as[row * HSTR + t];
                af[mi][1] = as[(row + 8) * HSTR + t];
                af[mi][2] = as[row * HSTR + t + 4];
                af[mi][3] = as[(row + 8) * HSTR + t + 4];
            }
            uint32_t bf[8][2];
#pragma unroll
            for (int ni = 0; ni < 8; ni++) {
                int nn = wn * 64 + ni * 8 + g;
                bf[ni][0] = bs[nn * HSTR + t];
                bf[ni][1] = bs[nn * HSTR + t + 4];
            }
#pragma unroll
            for (int mi = 0; mi < 2; mi++)
#pragma unroll
                for (int ni = 0; ni < 8; ni++)
                    mma16(acc[mi][ni][0], acc[mi][ni][1], acc[mi][ni][2], acc[mi][ni][3],
                          af[mi][0], af[mi][1], af[mi][2], af[mi][3],
                          bf[ni][0], bf[ni][1]);
        }

        // ---- store prefetched tile into other buffer ----
        if (nxt) {
            uint32_t* asn = As[buf ^ 1];
            uint32_t* bsn = Bs[buf ^ 1];
#pragma unroll
            for (int i = 0; i < 2; i++) {
                int r = lr + i * 64;
                *(uint2*)&asn[r * HSTR + lw] =
                    make_uint2(pkh2(ra[i].x, ra[i].y), pkh2(ra[i].z, ra[i].w));
                *(uint2*)&bsn[r * HSTR + lw] =
                    make_uint2(pkh2(rb[i].x, rb[i].y), pkh2(rb[i].z, rb[i].w));
            }
        }
        __syncthreads();
        buf ^= 1;
    }

    // ---- epilogue ----
#pragma unroll
    for (int mi = 0; mi < 2; mi++) {
#pragma unroll
        for (int rr = 0; rr < 2; rr++) {
            int m = m0 + wm * 32 + mi * 16 + g + rr * 8;
#pragma unroll
            for (int ni = 0; ni < 8; ni++) {
                int n = n0 + wn * 64 + ni * 8 + 2 * t;
                float v0 = acc[mi][ni][rr * 2 + 0];
                float v1 = acc[mi][ni][rr * 2 + 1];
                if (HAS_BIAS) { v0 += bias[n]; v1 += bias[n + 1]; }
                if (OMODE == 2) {
                    __half2* Ch = (__half2*)Cv;
                    Ch[((size_t)m * ldc + n) >> 1] = __floats2half2_rn(v0, v1);
                } else {
                    if (OMODE == 1) {
                        v0 = __uint_as_float(f2tf(v0));
                        v1 = __uint_as_float(f2tf(v1));
                    }
                    *(float2*)((float*)Cv + (size_t)m * ldc + n) = make_float2(v0, v1);
                }
            }
        }
    }
}

// ---------------------------------------------------------------------------
// Mask scan: set g_mask_allones=0 if any mask element is zero.
// ---------------------------------------------------------------------------
__global__ void mask_reset() { g_mask_allones = 1; }

__global__ void __launch_bounds__(512)
mask_scan(const int* __restrict__ mask)
{
    const int n4 = (SLEN * TLEN) / 4;
    int i = blockIdx.x * 512 + threadIdx.x;
    int bad = 0;
    for (; i < n4; i += gridDim.x * 512) {
        int4 v = ((const int4*)mask)[i];
        if (!(v.x && v.y && v.z && v.w)) bad = 1;
    }
    if (bad) g_mask_allones = 0;
}

// ---------------------------------------------------------------------------
// Fused flash attention: per CTA 128 query rows; stream K/V in T-tiles of 64.
// 512 threads = 16 warps: wm=warp>>1 (16 rows each), wn=warp&1.
// Q/K are fp16 (QK^T via m16n8k16); P tf32, V fp32 (PV via m16n8k8 tf32).
// SMEM words:
//   Qh [128][68] half2 rows (128 halves + pad)
//   Kh [ 64][68] half2 rows
//   Vs [2][64][136] fp32 [t][d]
//   Ps [128][68] tf32 [s][t]
//   red_m/red_s
// ---------------------------------------------------------------------------
#define BT 64
#define LDQH 68
#define LDKH 68
#define LDV 136
#define LDP 68
#define OFF_Q 0
#define OFF_K 8704
#define OFF_V 13056
#define VBUFW 8704
#define OFF_P 30464
#define OFF_RM 39168
#define OFF_RS 39424
#define SMEM_WORDS 39680

__global__ void __launch_bounds__(512, 1)
attn_fused(const __half* __restrict__ Q, const __half* __restrict__ K,
           const float* __restrict__ V, const int* __restrict__ mask,
           float* __restrict__ AO)
{
    extern __shared__ uint32_t sm[];
    const uint32_t smb = smem_u32(sm);

    const int tid  = threadIdx.x;
    const int lane = tid & 31;
    const int warp = tid >> 5;       // 0..15
    const int wm   = warp >> 1;      // 0..7
    const int wn   = warp & 1;       // 0..1
    const int g    = lane >> 2;
    const int t    = lane & 3;
    const int s0   = blockIdx.x * 128;
    const int bh   = blockIdx.y;
    const int zn   = bh >> 4, zh = bh & 15;
    const float scale = 0.08838834764831845f;
    const bool use_mask = (g_mask_allones == 0);

    const size_t qbase  = ((size_t)zn * SLEN + s0) * EDIM + (size_t)zh * DHEAD;
    const size_t kvbase = ((size_t)zn * TLEN) * EDIM + (size_t)zh * DHEAD;

    // ---- prologue: Q (fp16, 128 rows x 256B), K0 (fp16, 64 x 256B), V0 ----
#pragma unroll
    for (int i = 0; i < 4; i++) {
        int idx = tid + i * 512;                 // 0..2047
        int r = idx >> 4, c = idx & 15;          // 16B chunk = 8 halves
        cp16(smb + (OFF_Q + r * LDQH + c * 4) * 4,
             Q + qbase + (size_t)r * EDIM + c * 8);
    }
#pragma unroll
    for (int i = 0; i < 2; i++) {
        int idx = tid + i * 512;                 // 0..1023
        int r = idx >> 4, c = idx & 15;
        cp16(smb + (OFF_K + r * LDKH + c * 4) * 4,
             K + kvbase + (size_t)r * EDIM + c * 8);
    }
#pragma unroll
    for (int i = 0; i < 4; i++) {
        int idx = tid + i * 512;
        int r = idx >> 5, c = (idx & 31) << 2;
        cp16(smb + (OFF_V + r * LDV + c) * 4, V + kvbase + (size_t)r * EDIM + c);
    }
    asm volatile("cp.async.commit_group;");

    float Oa[8][4];
#pragma unroll
    for (int j = 0; j < 8; j++)
#pragma unroll
        for (int q = 0; q < 4; q++) Oa[j][q] = 0.0f;
    float m_run[2], l_run[2];
#pragma unroll
    for (int s = 0; s < 2; s++) { m_run[s] = NEG_INF; l_run[s] = 0.0f; }

    const int arow0 = wm * 16;

    for (int j = 0; j < TLEN / BT; j++) {
        asm volatile("cp.async.wait_group 0;" ::: "memory");
        __syncthreads();
        const int vb = j & 1;
        const int t0 = j * BT;

        // ---- S = Q K^T  (fp16 m16n8k16, 8 k-steps over DHEAD=128) ----
        float Sa[4][4];
#pragma unroll
        for (int n = 0; n < 4; n++)
#pragma unroll
            for (int q = 0; q < 4; q++) Sa[n][q] = 0.0f;

#pragma unroll
        for (int ks = 0; ks < 8; ks++) {
            const int w = ks * 8;                // half2 word offset
            uint32_t af[4];
            {
                int row = arow0 + g;
                af[0] = sm[OFF_Q + row * LDQH + w + t];
                af[1] = sm[OFF_Q + (row + 8) * LDQH + w + t];
                af[2] = sm[OFF_Q + row * LDQH + w + t + 4];
                af[3] = sm[OFF_Q + (row + 8) * LDQH + w + t + 4];
            }
            uint32_t bf[4][2];
#pragma unroll
            for (int ni = 0; ni < 4; ni++) {
                int n = wn * 32 + ni * 8 + g;
                bf[ni][0] = sm[OFF_K + n * LDKH + w + t];
                bf[ni][1] = sm[OFF_K + n * LDKH + w + t + 4];
            }
#pragma unroll
            for (int ni = 0; ni < 4; ni++)
                mma16(Sa[ni][0], Sa[ni][1], Sa[ni][2], Sa[ni][3],
                      af[0], af[1], af[2], af[3], bf[ni][0], bf[ni][1]);
        }

        // ---- scale + optional mask ----
#pragma unroll
        for (int ni = 0; ni < 4; ni++)
#pragma unroll
            for (int q = 0; q < 4; q++) Sa[ni][q] *= scale;

        if (use_mask) {
#pragma unroll
            for (int rr = 0; rr < 2; rr++) {
                int srow = s0 + arow0 + rr * 8 + g;
#pragma unroll
                for (int ni = 0; ni < 4; ni++)
#pragma unroll
                    for (int q = 0; q < 2; q++) {
                        int col = t0 + wn * 32 + ni * 8 + 2 * t + q;
                        if (__ldg(&mask[(size_t)col * SLEN + srow]) == 0)
                            Sa[ni][rr * 2 + q] = NEG_INF;
                    }
            }
        }

        // ---- row max ----
#pragma unroll
        for (int rr = 0; rr < 2; rr++) {
            float mx = NEG_INF;
#pragma unroll
            for (int ni = 0; ni < 4; ni++) {
                mx = fmaxf(mx, Sa[ni][rr * 2]);
                mx = fmaxf(mx, Sa[ni][rr * 2 + 1]);
            }
            mx = fmaxf(mx, __shfl_xor_sync(0xffffffffu, mx, 1));
            mx = fmaxf(mx, __shfl_xor_sync(0xffffffffu, mx, 2));
            if (t == 0) {
                int r = arow0 + rr * 8 + g;
                *(float*)&sm[OFF_RM + r * 2 + wn] = mx;
            }
        }
        __syncthreads();

        float m_new[2], alpha[2];
#pragma unroll
        for (int rr = 0; rr < 2; rr++) {
            int r = arow0 + rr * 8 + g;
            float tm = fmaxf(*(float*)&sm[OFF_RM + r * 2],
                             *(float*)&sm[OFF_RM + r * 2 + 1]);
            m_new[rr] = fmaxf(m_run[rr], tm);
            alpha[rr] = __expf(m_run[rr] - m_new[rr]);
            m_run[rr] = m_new[rr];
        }

        // ---- P = exp(S - m), write tf32 to SMEM, row sums ----
#pragma unroll
        for (int rr = 0; rr < 2; rr++) {
            int r = arow0 + rr * 8 + g;
            float sum = 0.0f;
#pragma unroll
            for (int ni = 0; ni < 4; ni++) {
                float p0 = __expf(Sa[ni][rr * 2]     - m_new[rr]);
                float p1 = __expf(Sa[ni][rr * 2 + 1] - m_new[rr]);
                sum += p0 + p1;
                uint2 pp = make_uint2(f2tf(p0), f2tf(p1));
                *(uint2*)&sm[OFF_P + r * LDP + wn * 32 + ni * 8 + 2 * t] = pp;
            }
            sum += __shfl_xor_sync(0xffffffffu, sum, 1);
            sum += __shfl_xor_sync(0xffffffffu, sum, 2);
            if (t == 0) *(float*)&sm[OFF_RS + r * 2 + wn] = sum;
        }
        __syncthreads();

#pragma unroll
        for (int rr = 0; rr < 2; rr++) {
            int r = arow0 + rr * 8 + g;
            float ts = *(float*)&sm[OFF_RS + r * 2] + *(float*)&sm[OFF_RS + r * 2 + 1];
            l_run[rr] = l_run[rr] * alpha[rr] + ts;
        }
        // rescale O
#pragma unroll
        for (int ni = 0; ni < 8; ni++)
#pragma unroll
            for (int q = 0; q < 4; q++)
                Oa[ni][q] *= alpha[q >> 1];

        // ---- prefetch next K/V tile (overlaps with PV) ----
        if (j + 1 < TLEN / BT) {
            const int tn = (j + 1) * BT;
            const int vn = vb ^ 1;
#pragma unroll
            for (int i = 0; i < 2; i++) {
                int idx = tid + i * 512;
                int r = idx >> 4, c = idx & 15;
                cp16(smb + (OFF_K + r * LDKH + c * 4) * 4,
                     K + kvbase + (size_t)(tn + r) * EDIM + c * 8);
            }
#pragma unroll
            for (int i = 0; i < 4; i++) {
                int idx = tid + i * 512;
                int r = idx >> 5, c = (idx & 31) << 2;
                cp16(smb + (OFF_V + vn * VBUFW + r * LDV + c) * 4,
                     V + kvbase + (size_t)(tn + r) * EDIM + c);
            }
            asm volatile("cp.async.commit_group;");
        }

        // ---- O += P V  (tf32 m16n8k8) ----
        const uint32_t* vs = &sm[OFF_V + vb * VBUFW];
#pragma unroll
        for (int ks = 0; ks < BT; ks += 8) {
            uint32_t af[4];
            {
                int row = arow0 + g;
                af[0] = sm[OFF_P + row * LDP + ks + t];
                af[1] = sm[OFF_P + (row + 8) * LDP + ks + t];
                af[2] = sm[OFF_P + row * LDP + ks + t + 4];
                af[3] = sm[OFF_P + (row + 8) * LDP + ks + t + 4];
            }
            uint32_t bf[8][2];
#pragma unroll
            for (int ni = 0; ni < 8; ni++) {
                int n = wn * 64 + ni * 8 + g;
                bf[ni][0] = vs[(ks + t) * LDV + n];
                bf[ni][1] = vs[(ks + t + 4) * LDV + n];
            }
#pragma unroll
            for (int ni = 0; ni < 8; ni++)
                mma8(Oa[ni][0], Oa[ni][1], Oa[ni][2], Oa[ni][3],
                     af[0], af[1], af[2], af[3], bf[ni][0], bf[ni][1]);
        }
    }

    // ---- epilogue: AO = O / l (tf32-rounded for the output projection) ----
#pragma unroll
    for (int rr = 0; rr < 2; rr++) {
        float inv = 1.0f / l_run[rr];
        int r = arow0 + rr * 8 + g;
#pragma unroll
        for (int ni = 0; ni < 8; ni++) {
            int col = wn * 64 + ni * 8 + 2 * t;
            float2 o = make_float2(
                __uint_as_float(f2tf(Oa[ni][rr * 2] * inv)),
                __uint_as_float(f2tf(Oa[ni][rr * 2 + 1] * inv)));
            *(float2*)(AO + qbase + (size_t)r * EDIM + col) = o;
        }
    }
}

// ---------------------------------------------------------------------------
// Host launcher
// ---------------------------------------------------------------------------
extern "C" void kernel_launch(void* const* d_in, const int* in_sizes, int n_in,
                              void* d_out, int out_size)
{
    const float* query = (const float*)d_in[0];
    const float* key   = (const float*)d_in[1];
    const float* value = (const float*)d_in[2];
    const int*   amask = (const int*)  d_in[3];
    const float* Wq    = (const float*)d_in[4];
    const float* bq    = (const float*)d_in[5];
    const float* Wk    = (const float*)d_in[6];
    const float* bk    = (const float*)d_in[7];
    const float* Wv    = (const float*)d_in[8];
    const float* bv    = (const float*)d_in[9];
    const float* Wp    = (const float*)d_in[10];
    const float* bp    = (const float*)d_in[11];
    float* out = (float*)d_out;

    __half *Qp, *Kp;
    float *Vp, *AOp;
    cudaGetSymbolAddress((void**)&Qp,  g_Q);
    cudaGetSymbolAddress((void**)&Kp,  g_K);
    cudaGetSymbolAddress((void**)&Vp,  g_V);
    cudaGetSymbolAddress((void**)&AOp, g_AO);

    const int M = NB * SLEN;   // 8192

    dim3 blk(256);
    dim3 gProj(EDIM / 128, M / 128, 1);          // 16 x 64

    cudaFuncSetAttribute(attn_fused,
                         cudaFuncAttributeMaxDynamicSharedMemorySize, SMEM_WORDS * 4);

    // 0) mask all-ones scan
    mask_reset<<<1, 1>>>();
    mask_scan<<<1024, 512>>>(amask);

    // 1-3) Q, K projections -> fp16; V projection -> fp32 tf32-rounded
    gemm_tc<true, 2><<<gProj, blk>>>(query, EDIM, Wq, EDIM, Qp, EDIM, bq, EDIM);
    gemm_tc<true, 2><<<gProj, blk>>>(key,   EDIM, Wk, EDIM, Kp, EDIM, bk, EDIM);
    gemm_tc<true, 1><<<gProj, blk>>>(value, EDIM, Wv, EDIM, Vp, EDIM, bv, EDIM);

    // 4) fused attention (fp16 QK^T, tf32 PV; 512 threads)
    {
        dim3 g(SLEN / 128, NB * HNUM);
        attn_fused<<<g, dim3(512), SMEM_WORDS * 4>>>(Qp, Kp, Vp, amask, AOp);
    }

    // 5) output projection in fp16 (full fp32 store)
    gemm_tc<true, 0><<<gProj, blk>>>(AOp, EDIM, Wp, EDIM, out, EDIM, bp, EDIM);
}